// round 3
// baseline (speedup 1.0000x reference)
#include <cuda_runtime.h>
#include <cuda_bf16.h>
#include <cstdint>

// out[b,n,d] = x[b,n] * W[n,d] + bias[n,d]   B=128, N=1024, D=512 fp32
//
// R2: register-reuse version hit DRAM=66%, kernel 41.8us (~6.4 TB/s writes).
// R3 deltas: B_PER_BLK 32->64 (halve residual W/b L2 reads), streaming
// stores (__stcs, evict-first) so the write-once output doesn't pollute L2
// and write sectors drain eagerly.

static constexpr int B_ = 128;
static constexpr int N_ = 1024;
static constexpr int D4 = 512 / 4;            // 128 float4 per row
static constexpr int ND4 = N_ * D4;           // 131072 float4 per batch
static constexpr int B_PER_BLK = 64;          // batch rows per block

__global__ __launch_bounds__(128) void bcast_fma_reuse_kernel(
    const float*  __restrict__ x,    // [B, N]
    const float4* __restrict__ W4,   // [N, D4]
    const float4* __restrict__ b4,   // [N, D4]
    float4*       __restrict__ out4) // [B, N, D4]
{
    const unsigned int n   = blockIdx.x;          // 0..1023
    const unsigned int tid = threadIdx.x;         // 0..127 == d4
    const unsigned int b0  = blockIdx.y * B_PER_BLK;
    const unsigned int nd4 = n * D4 + tid;

    // Weights/bias for this (n, d4): loaded once, reused 64x from registers.
    const float4 w = W4[nd4];
    const float4 c = b4[nd4];

    // Stage the 64 x-scalars for this block's batch slice in shared memory.
    __shared__ float xs[B_PER_BLK];
    if (tid < B_PER_BLK) xs[tid] = __ldg(&x[(b0 + tid) * N_ + n]);
    __syncthreads();

    unsigned int o_idx = b0 * ND4 + nd4;
    #pragma unroll 16
    for (int i = 0; i < B_PER_BLK; ++i) {
        const float s = xs[i];
        float4 o;
        o.x = fmaf(s, w.x, c.x);
        o.y = fmaf(s, w.y, c.y);
        o.z = fmaf(s, w.z, c.z);
        o.w = fmaf(s, w.w, c.w);
        __stcs(&out4[o_idx], o);    // streaming store: evict-first, write-once data
        o_idx += ND4;
    }
}

extern "C" void kernel_launch(void* const* d_in, const int* in_sizes, int n_in,
                              void* d_out, int out_size) {
    const float*  x  = (const float*)d_in[0];
    const float4* W4 = (const float4*)d_in[1];
    const float4* b4 = (const float4*)d_in[2];
    float4* out4 = (float4*)d_out;

    dim3 grid(N_, B_ / B_PER_BLK);   // 1024 x 2 = 2048 blocks
    bcast_fma_reuse_kernel<<<grid, 128>>>(x, W4, b4, out4);
}